// round 6
// baseline (speedup 1.0000x reference)
#include <cuda_runtime.h>
#include <cuda_bf16.h>
#include <math.h>

#define S_ 8192
#define D_ 2048
#define H_ 2048
#define F_ 8192
#define NCHUNK 64
#define CHUNK_LEN 128   // S_ / NCHUNK

// ---------------- scratch (static device globals; no allocation) ----------------
__device__ float g_xh[(size_t)S_ * H_];     // xh, then b-coeff
__device__ float g_apre[(size_t)S_ * H_];   // pre-a, then a-coeff
__device__ float g_gpre[(size_t)S_ * H_];   // pre-g, then h (scan output)
__device__ float g_res[(size_t)S_ * D_];    // residual (branch 1, then branch 2)
__device__ float g_xn[(size_t)S_ * D_];     // normalized x after branch 1
__device__ float g_t[(size_t)S_ * F_];      // FFN hidden (gelu applied in epilogue)
__device__ float g_cA[(size_t)NCHUNK * H_];
__device__ float g_cB[(size_t)NCHUNK * H_];
__device__ float g_carry[(size_t)NCHUNK * H_];
__device__ float g_prob[S_];

// ---------------- helpers ----------------
__device__ __forceinline__ float sigmoidf_(float x) {
    return 1.0f / (1.0f + expf(-x));
}

__device__ __forceinline__ float log_sigmoidf_(float x) {
    // -softplus(-x), numerically stable
    return (x >= 0.0f) ? -log1pf(expf(-x)) : (x - log1pf(expf(x)));
}

__device__ __forceinline__ float gelu_tanh_(float x) {
    float x3 = x * x * x;
    float t = tanhf(0.7978845608028654f * (x + 0.044715f * x3));
    return 0.5f * x * (1.0f + t);
}

__device__ __forceinline__ float block_reduce_sum_256(float v) {
    __shared__ float red[8];
    int lane = threadIdx.x & 31;
    int w = threadIdx.x >> 5;
    #pragma unroll
    for (int o = 16; o; o >>= 1) v += __shfl_xor_sync(0xffffffffu, v, o);
    if (lane == 0) red[w] = v;
    __syncthreads();
    if (w == 0) {
        v = (lane < 8) ? red[lane] : 0.0f;
        #pragma unroll
        for (int o = 4; o; o >>= 1) v += __shfl_xor_sync(0xffffffffu, v, o);
        if (lane == 0) red[0] = v;
    }
    __syncthreads();
    return red[0];
}

// ---------------- SGEMM: C[m,n] = sum_k A[m,k] * W[n,k] + bias[n] (opt gelu) ----------------
// A: [M,K] row-major; W: [N,K] row-major. M,N,K all multiples of tile dims.
#define BM 128
#define BN 128
#define BK 16
#define TM 8
#define TN 8

__global__ __launch_bounds__(256) void sgemm_nt(
    const float* __restrict__ A, const float* __restrict__ W,
    const float* __restrict__ bias, float* __restrict__ C,
    int M, int N, int K, int fuse_gelu)
{
    __shared__ float As[BK][BM];
    __shared__ float Bs[BK][BN];

    const int tid = threadIdx.x;          // 0..255
    const int tx = tid & 15;              // 0..15 (N dir)
    const int ty = tid >> 4;              // 0..15 (M dir)
    const int row0 = blockIdx.y * BM;
    const int col0 = blockIdx.x * BN;

    float acc[TM][TN];
    #pragma unroll
    for (int i = 0; i < TM; i++)
        #pragma unroll
        for (int j = 0; j < TN; j++) acc[i][j] = 0.0f;

    for (int k0 = 0; k0 < K; k0 += BK) {
        // load A tile [BM x BK] and W tile [BN x BK], transposed into smem [BK][128]
        #pragma unroll
        for (int i = 0; i < 2; i++) {
            int id = tid + i * 256;       // 0..511
            int r  = id >> 2;             // 0..127
            int c4 = id & 3;              // 0..3
            float4 va = *reinterpret_cast<const float4*>(&A[(size_t)(row0 + r) * K + k0 + c4 * 4]);
            As[c4 * 4 + 0][r] = va.x;
            As[c4 * 4 + 1][r] = va.y;
            As[c4 * 4 + 2][r] = va.z;
            As[c4 * 4 + 3][r] = va.w;
            float4 vb = *reinterpret_cast<const float4*>(&W[(size_t)(col0 + r) * K + k0 + c4 * 4]);
            Bs[c4 * 4 + 0][r] = vb.x;
            Bs[c4 * 4 + 1][r] = vb.y;
            Bs[c4 * 4 + 2][r] = vb.z;
            Bs[c4 * 4 + 3][r] = vb.w;
        }
        __syncthreads();

        #pragma unroll
        for (int kk = 0; kk < BK; kk++) {
            float af[TM], bf[TN];
            *reinterpret_cast<float4*>(&af[0]) = *reinterpret_cast<const float4*>(&As[kk][ty * TM]);
            *reinterpret_cast<float4*>(&af[4]) = *reinterpret_cast<const float4*>(&As[kk][ty * TM + 4]);
            *reinterpret_cast<float4*>(&bf[0]) = *reinterpret_cast<const float4*>(&Bs[kk][tx * TN]);
            *reinterpret_cast<float4*>(&bf[4]) = *reinterpret_cast<const float4*>(&Bs[kk][tx * TN + 4]);
            #pragma unroll
            for (int i = 0; i < TM; i++)
                #pragma unroll
                for (int j = 0; j < TN; j++)
                    acc[i][j] = fmaf(af[i], bf[j], acc[i][j]);
        }
        __syncthreads();
    }

    // epilogue: bias (+gelu) and vectorized store
    #pragma unroll
    for (int i = 0; i < TM; i++) {
        int r = row0 + ty * TM + i;
        #pragma unroll
        for (int j = 0; j < TN; j += 4) {
            int c = col0 + tx * TN + j;
            float4 v;
            v.x = acc[i][j + 0] + bias[c + 0];
            v.y = acc[i][j + 1] + bias[c + 1];
            v.z = acc[i][j + 2] + bias[c + 2];
            v.w = acc[i][j + 3] + bias[c + 3];
            if (fuse_gelu) {
                v.x = gelu_tanh_(v.x);
                v.y = gelu_tanh_(v.y);
                v.z = gelu_tanh_(v.z);
                v.w = gelu_tanh_(v.w);
            }
            *reinterpret_cast<float4*>(&C[(size_t)r * N + c]) = v;
        }
    }
}

// ---------------- elementwise: compute (a, b) scan coefficients ----------------
// in: g_xh = xh, g_apre = pre_a, g_gpre = pre_g; out: g_apre = a, g_xh = b
__global__ void compute_ab(float* __restrict__ xh, float* __restrict__ ap,
                           const float* __restrict__ gp, const float* __restrict__ lam,
                           size_t n, int H)
{
    size_t i = (size_t)blockIdx.x * blockDim.x + threadIdx.x;
    if (i >= n) return;
    int h = (int)(i % (size_t)H);
    float r = sigmoidf_(ap[i]);
    float g = sigmoidf_(gp[i]);
    float ls = log_sigmoidf_(lam[h]);
    float la = 8.0f * r * ls;            // C_GATE = 8
    float a = expf(la);
    float omega = 1.0f - expf(2.0f * la);
    if (omega < 0.0f) omega = 0.0f;
    float b = sqrtf(omega) * (g * xh[i]);
    ap[i] = a;
    xh[i] = b;
}

// ---------------- blocked linear scan: h_t = a_t h_{t-1} + b_t ----------------
__global__ void scan_chunk_reduce(const float* __restrict__ a, const float* __restrict__ b,
                                  float* __restrict__ cA, float* __restrict__ cB, int H)
{
    int h = blockIdx.x * blockDim.x + threadIdx.x;   // column
    int c = blockIdx.y;                               // chunk
    size_t base = (size_t)c * CHUNK_LEN * H + h;
    float A = 1.0f, B = 0.0f;
    #pragma unroll 4
    for (int t = 0; t < CHUNK_LEN; t++) {
        float at = a[base + (size_t)t * H];
        float bt = b[base + (size_t)t * H];
        A = A * at;
        B = at * B + bt;
    }
    cA[(size_t)c * H + h] = A;
    cB[(size_t)c * H + h] = B;
}

__global__ void scan_carry(const float* __restrict__ cA, const float* __restrict__ cB,
                           float* __restrict__ carry, int H)
{
    int h = blockIdx.x * blockDim.x + threadIdx.x;
    float s = 0.0f;                                   // initial state h_0 = 0
    for (int c = 0; c < NCHUNK; c++) {
        carry[(size_t)c * H + h] = s;
        s = cA[(size_t)c * H + h] * s + cB[(size_t)c * H + h];
    }
}

__global__ void scan_apply(const float* __restrict__ a, const float* __restrict__ b,
                           const float* __restrict__ carry, float* __restrict__ hout, int H)
{
    int h = blockIdx.x * blockDim.x + threadIdx.x;
    int c = blockIdx.y;
    size_t base = (size_t)c * CHUNK_LEN * H + h;
    float s = carry[(size_t)c * H + h];
    #pragma unroll 4
    for (int t = 0; t < CHUNK_LEN; t++) {
        s = a[base + (size_t)t * H] * s + b[base + (size_t)t * H];
        hout[base + (size_t)t * H] = s;
    }
}

// ---------------- per-row gate probability: sigmoid(res . w + b) ----------------
__global__ void rowdot_sigmoid(const float* __restrict__ R, const float* __restrict__ w,
                               const float* __restrict__ b, float* __restrict__ prob, int D)
{
    int s = blockIdx.x;
    const float* row = R + (size_t)s * D;
    float sum = 0.0f;
    for (int c = threadIdx.x; c < D; c += blockDim.x) sum += row[c] * w[c];
    sum = block_reduce_sum_256(sum);
    if (threadIdx.x == 0) prob[s] = sigmoidf_(sum + b[0]);
}

// ---------------- gated residual add + RMSNorm (per row, D=2048, 256 thr) ----------------
__global__ void gate_norm(const float* __restrict__ X, const float* __restrict__ R,
                          const float* __restrict__ prob, const float* __restrict__ u,
                          const float* __restrict__ nw, const float* __restrict__ nb,
                          float* __restrict__ out, int D)
{
    int s = blockIdx.x;
    bool gate = u[s] < prob[s];
    const float* xr = X + (size_t)s * D;
    const float* rr = R + (size_t)s * D;
    float vals[8];
    float ss = 0.0f;
    #pragma unroll
    for (int i = 0; i < 8; i++) {
        int c = threadIdx.x + i * 256;
        float v = xr[c] + (gate ? rr[c] : 0.0f);
        vals[i] = v;
        ss += v * v;
    }
    ss = block_reduce_sum_256(ss);
    float inv = rsqrtf(ss / (float)D + 1e-6f);
    #pragma unroll
    for (int i = 0; i < 8; i++) {
        int c = threadIdx.x + i * 256;
        out[(size_t)s * D + c] = vals[i] * inv * nw[c] + nb[c];
    }
}

// ---------------- launch ----------------
extern "C" void kernel_launch(void* const* d_in, const int* in_sizes, int n_in,
                              void* d_out, int out_size)
{
    const float* x      = (const float*)d_in[0];
    const float* W_in   = (const float*)d_in[1];
    const float* b_in   = (const float*)d_in[2];
    const float* W_a    = (const float*)d_in[3];
    const float* b_a    = (const float*)d_in[4];
    const float* W_g    = (const float*)d_in[5];
    const float* b_g    = (const float*)d_in[6];
    const float* lam    = (const float*)d_in[7];
    const float* W_out  = (const float*)d_in[8];
    const float* b_out  = (const float*)d_in[9];
    const float* ffn_w1 = (const float*)d_in[10];
    const float* ffn_b1 = (const float*)d_in[11];
    const float* ffn_w2 = (const float*)d_in[12];
    const float* ffn_b2 = (const float*)d_in[13];
    const float* act1_w = (const float*)d_in[14];
    const float* act1_b = (const float*)d_in[15];
    const float* act2_w = (const float*)d_in[16];
    const float* act2_b = (const float*)d_in[17];
    const float* n1w    = (const float*)d_in[18];
    const float* n1b    = (const float*)d_in[19];
    const float* n2w    = (const float*)d_in[20];
    const float* n2b    = (const float*)d_in[21];
    const float* u1     = (const float*)d_in[22];
    const float* u2     = (const float*)d_in[23];
    float* out = (float*)d_out;

    float *p_xh, *p_apre, *p_gpre, *p_res, *p_xn, *p_t, *p_cA, *p_cB, *p_carry, *p_prob;
    cudaGetSymbolAddress((void**)&p_xh,    g_xh);
    cudaGetSymbolAddress((void**)&p_apre,  g_apre);
    cudaGetSymbolAddress((void**)&p_gpre,  g_gpre);
    cudaGetSymbolAddress((void**)&p_res,   g_res);
    cudaGetSymbolAddress((void**)&p_xn,    g_xn);
    cudaGetSymbolAddress((void**)&p_t,     g_t);
    cudaGetSymbolAddress((void**)&p_cA,    g_cA);
    cudaGetSymbolAddress((void**)&p_cB,    g_cB);
    cudaGetSymbolAddress((void**)&p_carry, g_carry);
    cudaGetSymbolAddress((void**)&p_prob,  g_prob);

    dim3 blk(256);
    dim3 g_DH(H_ / BN, S_ / BM);   // N=2048 output GEMMs
    dim3 g_F(F_ / BN, S_ / BM);    // N=8192 output GEMM

    // --- RG-LRU branch ---
    sgemm_nt<<<g_DH, blk>>>(x, W_in, b_in, p_xh,   S_, H_, D_, 0);
    sgemm_nt<<<g_DH, blk>>>(x, W_a,  b_a,  p_apre, S_, H_, D_, 0);
    sgemm_nt<<<g_DH, blk>>>(x, W_g,  b_g,  p_gpre, S_, H_, D_, 0);

    size_t nSH = (size_t)S_ * H_;
    compute_ab<<<(unsigned)((nSH + 255) / 256), blk>>>(p_xh, p_apre, p_gpre, lam, nSH, H_);

    dim3 g_scan(H_ / 256, NCHUNK);
    scan_chunk_reduce<<<g_scan, blk>>>(p_apre, p_xh, p_cA, p_cB, H_);
    scan_carry<<<H_ / 256, blk>>>(p_cA, p_cB, p_carry, H_);
    scan_apply<<<g_scan, blk>>>(p_apre, p_xh, p_carry, p_gpre, H_);   // h -> g_gpre

    sgemm_nt<<<g_DH, blk>>>(p_gpre, W_out, b_out, p_res, S_, D_, H_, 0);

    rowdot_sigmoid<<<S_, blk>>>(p_res, act1_w, act1_b, p_prob, D_);
    gate_norm<<<S_, blk>>>(x, p_res, p_prob, u1, n1w, n1b, p_xn, D_);

    // --- FFN branch ---
    sgemm_nt<<<g_F,  blk>>>(p_xn, ffn_w1, ffn_b1, p_t,   S_, F_, D_, 1);  // fused gelu
    sgemm_nt<<<g_DH, blk>>>(p_t,  ffn_w2, ffn_b2, p_res, S_, D_, F_, 0);

    rowdot_sigmoid<<<S_, blk>>>(p_res, act2_w, act2_b, p_prob, D_);
    gate_norm<<<S_, blk>>>(p_xn, p_res, p_prob, u2, n2w, n2b, out, D_);
}